// round 5
// baseline (speedup 1.0000x reference)
#include <cuda_runtime.h>
#include <cuda_bf16.h>
#include <cstdint>

#define NB 16
#define CIN 512
#define COUT 256
#define HH 32
#define WW 32
#define EPSV 1e-5f

__device__ __align__(16) __nv_bfloat16 g_xh[16384ull * 512];   // [p][ci] K-major hi
__device__ __align__(16) __nv_bfloat16 g_xl[16384ull * 512];   // lo
__device__ __align__(16) __nv_bfloat16 g_Bh[36ull * 256 * 512];
__device__ __align__(16) __nv_bfloat16 g_Bl[36ull * 256 * 512];
__device__ float g_scratch[4ull * NB * COUT * HH * WW]; // [conv][n][c][1024]
__device__ float g_scale[COUT];
__device__ float g_shift[COUT];

__constant__ int c_taps[4][9] = {
    {0,1,2,3,4,5,6,7,8}, {0,1,2,3,4,5,0,0,0}, {0,1,3,4,6,7,0,0,0}, {0,1,3,4,0,0,0,0,0}};
__constant__ int c_ntaps[4] = {9, 6, 6, 4};

__device__ __forceinline__ uint32_t smem_u32(const void* p) {
    uint32_t a;
    asm("{ .reg .u64 t; cvta.to.shared.u64 t, %1; cvt.u32.u64 %0, t; }" : "=r"(a) : "l"(p));
    return a;
}

#define ROWB  144u    // 128B data + 16B pad: conflict-free ldmatrix
#define TILEB 18432u  // 128 * 144
#define STAGEB 73728u // 4 tiles (Ah, Al, Bh, Bl)
#define SMEM_SZ (3u * STAGEB)

__device__ __forceinline__ void cpa(uint32_t dst, const void* src) {
    asm volatile("cp.async.cg.shared.global [%0], [%1], 16;" :: "r"(dst), "l"(src));
}
__device__ __forceinline__ void cpaz(uint32_t dst, const void* src, int ok) {
    asm volatile("cp.async.cg.shared.global [%0], [%1], 16, %2;"
                 :: "r"(dst), "l"(src), "r"(ok ? 16 : 0));
}
__device__ __forceinline__ void ldsm4(uint32_t& r0, uint32_t& r1, uint32_t& r2, uint32_t& r3,
                                      uint32_t a) {
    asm volatile("ldmatrix.sync.aligned.m8n8.x4.shared.b16 {%0,%1,%2,%3}, [%4];"
                 : "=r"(r0), "=r"(r1), "=r"(r2), "=r"(r3) : "r"(a));
}
__device__ __forceinline__ void mma_bf16(float* d, const uint32_t* a, uint32_t b0, uint32_t b1) {
    asm volatile(
        "mma.sync.aligned.m16n8k16.row.col.f32.bf16.bf16.f32 "
        "{%0,%1,%2,%3}, {%4,%5,%6,%7}, {%8,%9}, {%0,%1,%2,%3};"
        : "+f"(d[0]), "+f"(d[1]), "+f"(d[2]), "+f"(d[3])
        : "r"(a[0]), "r"(a[1]), "r"(a[2]), "r"(a[3]), "r"(b0), "r"(b1));
}

// ---------------------------------------------------------------------------
__global__ void prep_w(const float* __restrict__ w1, const float* __restrict__ w2,
                       const float* __restrict__ w3, const float* __restrict__ w4) {
    const int total = 36 * 256 * 512;
    for (int idx = blockIdx.x * blockDim.x + threadIdx.x; idx < total;
         idx += gridDim.x * blockDim.x) {
        int ci = idx & 511, co = (idx >> 9) & 255;
        int tap = (idx >> 17) % 9, conv = idx / (9 << 17);
        int dy = tap / 3, dx = tap % 3;
        int kh = 3 - (conv & 1), kw = 3 - ((conv >> 1) & 1);
        float v = 0.f;
        if (dy < kh && dx < kw) {
            const float* w = (conv == 0) ? w1 : (conv == 1) ? w2 : (conv == 2) ? w3 : w4;
            v = w[((co * CIN + ci) * kh + dy) * kw + dx];
        }
        __nv_bfloat16 hi = __float2bfloat16(v);
        g_Bh[idx] = hi;
        g_Bl[idx] = __float2bfloat16(v - __bfloat162float(hi));
    }
}

// Transpose x -> K-major bf16 hi/lo [n*1024 + i*32 + j][ci]; grid (8, 16)
__global__ void prep_x(const float* __restrict__ x) {
    __shared__ float S[128][33];
    const int rb = blockIdx.x, n = blockIdx.y;
    const int tid = threadIdx.x;
    const size_t outbase = ((size_t)n * 1024 + rb * 128) * 512;
    for (int cic = 0; cic < 16; cic++) {
        const int ci0 = cic * 32;
        __syncthreads();
#pragma unroll
        for (int k = 0; k < 16; k++) {
            int idx = tid + k * 256;
            int ci = idx >> 7, pl = idx & 127;
            int i = rb * 4 + (pl >> 5), j = pl & 31;
            S[pl][ci] = x[(((size_t)n * CIN + ci0 + ci) * HH + i) * WW + j];
        }
        __syncthreads();
#pragma unroll
        for (int k = 0; k < 16; k++) {
            int idx = tid + k * 256;
            int pl = idx >> 5, ci = idx & 31;
            float f = S[pl][ci];
            __nv_bfloat16 hi = __float2bfloat16(f);
            size_t o = outbase + (size_t)pl * 512 + ci0 + ci;
            g_xh[o] = hi;
            g_xl[o] = __float2bfloat16(f - __bfloat162float(hi));
        }
    }
}

// ---------------------------------------------------------------------------
__device__ __forceinline__ void load_stage(uint32_t stage, int conv, int p0, int c0,
                                           int s, int tid) {
    const int tap = c_taps[conv][s >> 3];
    const int ci0 = (s & 7) << 6;
    const int dy = tap / 3 - 1, dx = tap % 3 - 1;
    const int seg = tid & 7, base = tid >> 3;     // base in [0,32)
    const int j = base & 31;
    const int jj = j + dx;
    const int jok = (unsigned)jj < 32u;
    const size_t bbase = ((size_t)(conv * 9 + tap) * 256 + c0) * 512 + ci0 + seg * 8;
#pragma unroll
    for (int kq = 0; kq < 4; kq++) {
        const int row = base + kq * 32;
        const int p = p0 + row;
        const int i = (p >> 5) & 31;
        const int ii = i + dy;
        const int ok = jok & ((unsigned)ii < 32u);
        const int iic = ok ? ii : 0, jjc = ok ? jj : 0;
        const size_t srow = (((size_t)(p >> 10) * 1024) + iic * 32 + jjc) * 512 + ci0 + seg * 8;
        const uint32_t d0 = stage + row * ROWB + seg * 16;
        cpaz(d0,         g_xh + srow, ok);
        cpaz(d0 + TILEB, g_xl + srow, ok);
        cpa(d0 + 2 * TILEB, g_Bh + bbase + (size_t)row * 512);
        cpa(d0 + 3 * TILEB, g_Bl + bbase + (size_t)row * 512);
    }
}

__global__ __launch_bounds__(256, 1)
void conv_mma(const float* __restrict__ b1, const float* __restrict__ b2,
              const float* __restrict__ b3, const float* __restrict__ b4) {
    extern __shared__ char smem[];
    const uint32_t sb = smem_u32(smem);
    const int tid = threadIdx.x, wid = tid >> 5, lane = tid & 31;
    const int conv = blockIdx.x >> 8;
    const int c0 = ((blockIdx.x >> 7) & 1) * 128;
    const int p0 = (blockIdx.x & 127) * 128;
    const int S = c_ntaps[conv] * 8;

    const int m0 = (wid & 3) * 32;
    const int n0 = (wid >> 2) * 64;

    float d[2][8][4];
#pragma unroll
    for (int mt = 0; mt < 2; mt++)
#pragma unroll
        for (int nt = 0; nt < 8; nt++)
#pragma unroll
            for (int e = 0; e < 4; e++) d[mt][nt][e] = 0.f;

    load_stage(sb, conv, p0, c0, 0, tid);
    asm volatile("cp.async.commit_group;");
    load_stage(sb + STAGEB, conv, p0, c0, 1, tid);
    asm volatile("cp.async.commit_group;");

    int cb = 0, nb = 2;   // current compute buffer, next load buffer
    for (int s = 0; s < S; s++) {
        if (s + 2 < S) {
            load_stage(sb + (uint32_t)nb * STAGEB, conv, p0, c0, s + 2, tid);
            asm volatile("cp.async.commit_group;");
            asm volatile("cp.async.wait_group 2;");
        } else if (s + 1 < S) {
            asm volatile("cp.async.wait_group 1;");
        } else {
            asm volatile("cp.async.wait_group 0;");
        }
        __syncthreads();

        const uint32_t stage = sb + (uint32_t)cb * STAGEB;
        uint32_t aH[2][4], aL[2][4], bH[16], bL[16];
#pragma unroll
        for (int kk = 0; kk < 4; kk++) {
            const uint32_t arow = m0 + (lane & 15);
            const uint32_t akof = kk * 32 + ((lane >> 4) << 4);
            uint32_t aa = stage + arow * ROWB + akof;
            ldsm4(aH[0][0], aH[0][1], aH[0][2], aH[0][3], aa);
            ldsm4(aH[1][0], aH[1][1], aH[1][2], aH[1][3], aa + 16 * ROWB);
            ldsm4(aL[0][0], aL[0][1], aL[0][2], aL[0][3], aa + TILEB);
            ldsm4(aL[1][0], aL[1][1], aL[1][2], aL[1][3], aa + TILEB + 16 * ROWB);
            const uint32_t brow = n0 + ((lane >> 4) << 3) + (lane & 7);
            const uint32_t bkof = kk * 32 + (((lane >> 3) & 1) << 4);
#pragma unroll
            for (int bt = 0; bt < 4; bt++) {
                uint32_t ba = stage + 2 * TILEB + (brow + bt * 16) * ROWB + bkof;
                ldsm4(bH[bt * 4], bH[bt * 4 + 1], bH[bt * 4 + 2], bH[bt * 4 + 3], ba);
                ldsm4(bL[bt * 4], bL[bt * 4 + 1], bL[bt * 4 + 2], bL[bt * 4 + 3], ba + TILEB);
            }
#pragma unroll
            for (int mt = 0; mt < 2; mt++)
#pragma unroll
                for (int nt = 0; nt < 8; nt++) {
                    mma_bf16(d[mt][nt], aH[mt], bH[nt * 2], bH[nt * 2 + 1]);
                    mma_bf16(d[mt][nt], aH[mt], bL[nt * 2], bL[nt * 2 + 1]);
                    mma_bf16(d[mt][nt], aL[mt], bH[nt * 2], bH[nt * 2 + 1]);
                }
        }
        __syncthreads();
        cb = (cb == 2) ? 0 : cb + 1;
        nb = (nb == 2) ? 0 : nb + 1;
    }

    // Epilogue: add bias, store to scratch
    const float* bias = (conv == 0) ? b1 : (conv == 1) ? b2 : (conv == 2) ? b3 : b4;
#pragma unroll
    for (int mt = 0; mt < 2; mt++)
#pragma unroll
        for (int nt = 0; nt < 8; nt++) {
            int prow = p0 + m0 + mt * 16 + (lane >> 2);
            int co = c0 + n0 + nt * 8 + (lane & 3) * 2;
            float bv0 = __ldg(bias + co), bv1 = __ldg(bias + co + 1);
            size_t base = ((size_t)(conv * NB + (prow >> 10)) * COUT + co) * 1024 + (prow & 1023);
            g_scratch[base]            = d[mt][nt][0] + bv0;
            g_scratch[base + 1024]     = d[mt][nt][1] + bv1;
            g_scratch[base + 8]        = d[mt][nt][2] + bv0;
            g_scratch[base + 1024 + 8] = d[mt][nt][3] + bv1;
        }
}

// BN stats: one block per channel, deterministic tree reduction
__global__ void stats_k(const float* __restrict__ gamma, const float* __restrict__ beta) {
    __shared__ float sS[256], sQ[256];
    const int c = blockIdx.x, tid = threadIdx.x;
    float S = 0.f, Q = 0.f;
    for (int idx = tid; idx < 65536; idx += 256) {
        int sp = idx & 1023, cn = idx >> 10;
        float v = g_scratch[((size_t)cn * COUT + c) * 1024 + sp];
        S += v; Q += v * v;
    }
    sS[tid] = S; sQ[tid] = Q;
    __syncthreads();
    for (int off = 128; off > 0; off >>= 1) {
        if (tid < off) { sS[tid] += sS[tid + off]; sQ[tid] += sQ[tid + off]; }
        __syncthreads();
    }
    if (tid == 0) {
        const float inv = 1.f / 65536.f;
        float mean = sS[0] * inv;
        float var = sQ[0] * inv - mean * mean;
        float sc = gamma[c] * rsqrtf(var + EPSV);
        g_scale[c] = sc;
        g_shift[c] = beta[c] - mean * sc;
    }
}

__global__ void apply_k(float* __restrict__ out) {
    int t = blockIdx.x * blockDim.x + threadIdx.x;
    int base = t * 4;
    if (base >= NB * COUT * 64 * 64) return;
    int J0 = base & 63, I = (base >> 6) & 63, c = (base >> 12) & 255, n = base >> 20;
    int i = I >> 1, pr = I & 1;
    float sc = g_scale[c], sh = g_shift[c];
    float v[4];
#pragma unroll
    for (int e = 0; e < 4; e++) {
        int J = J0 + e;
        int conv = pr + ((J & 1) << 1);
        int j = J >> 1;
        float o = g_scratch[((((size_t)conv * NB + n) * COUT + c) * HH + i) * WW + j];
        float y = o * sc + sh;
        v[e] = y > 0.f ? y : 0.f;
    }
    *(float4*)(out + base) = make_float4(v[0], v[1], v[2], v[3]);
}

extern "C" void kernel_launch(void* const* d_in, const int* in_sizes, int n_in,
                              void* d_out, int out_size) {
    const float* x     = (const float*)d_in[0];
    const float* w1    = (const float*)d_in[1];
    const float* b1    = (const float*)d_in[2];
    const float* w2    = (const float*)d_in[3];
    const float* b2    = (const float*)d_in[4];
    const float* w3    = (const float*)d_in[5];
    const float* b3    = (const float*)d_in[6];
    const float* w4    = (const float*)d_in[7];
    const float* b4    = (const float*)d_in[8];
    const float* gamma = (const float*)d_in[9];
    const float* beta  = (const float*)d_in[10];
    float* out = (float*)d_out;

    cudaFuncSetAttribute(conv_mma, cudaFuncAttributeMaxDynamicSharedMemorySize, SMEM_SZ);
    prep_w<<<2048, 256>>>(w1, w2, w3, w4);
    prep_x<<<dim3(8, 16), 256>>>(x);
    conv_mma<<<1024, 256, SMEM_SZ>>>(b1, b2, b3, b4);
    stats_k<<<COUT, 256>>>(gamma, beta);
    apply_k<<<(NB * COUT * 64 * 64 / 4 + 255) / 256, 256>>>(out);
}

// round 6
// speedup vs baseline: 2.7100x; 2.7100x over previous
#include <cuda_runtime.h>
#include <cuda_fp16.h>
#include <cstdint>

#define NB 16
#define CIN 512
#define COUT 256
#define HH 32
#define WW 32
#define EPSV 1e-5f

__device__ __align__(16) __half g_A[9ull * 16384 * 512];   // im2col fp16 [tap][p][ci]
__device__ __align__(16) __half g_B[36ull * 256 * 512];    // weights fp16 [(conv*9+tap)][co][ci]
__device__ float g_scratch[4ull * NB * COUT * HH * WW];    // [conv][n][c][1024]
__device__ float g_scale[COUT];
__device__ float g_shift[COUT];

__constant__ int c_taps[4][9] = {
    {0,1,2,3,4,5,6,7,8}, {0,1,2,3,4,5,0,0,0}, {0,1,3,4,6,7,0,0,0}, {0,1,3,4,0,0,0,0,0}};
__constant__ int c_ntaps[4] = {9, 6, 6, 4};

__device__ __forceinline__ uint32_t smem_u32(const void* p) {
    uint32_t a;
    asm("{ .reg .u64 t; cvta.to.shared.u64 t, %1; cvt.u32.u64 %0, t; }" : "=r"(a) : "l"(p));
    return a;
}

#define ROWB  144u     // 128B data + 16B pad: conflict-free ldmatrix, 16B-aligned
#define TILEB 18432u   // 128 rows * 144B
#define STAGEB 36864u  // A tile + B tile
#define NSTG 4
#define SMEM_SZ (NSTG * STAGEB)

__device__ __forceinline__ void cpa(uint32_t dst, const void* src) {
    asm volatile("cp.async.cg.shared.global [%0], [%1], 16;" :: "r"(dst), "l"(src));
}
__device__ __forceinline__ void ldsm4(uint32_t& r0, uint32_t& r1, uint32_t& r2, uint32_t& r3,
                                      uint32_t a) {
    asm volatile("ldmatrix.sync.aligned.m8n8.x4.shared.b16 {%0,%1,%2,%3}, [%4];"
                 : "=r"(r0), "=r"(r1), "=r"(r2), "=r"(r3) : "r"(a));
}
__device__ __forceinline__ void mma_f16(float* d, const uint32_t* a, uint32_t b0, uint32_t b1) {
    asm volatile(
        "mma.sync.aligned.m16n8k16.row.col.f32.f16.f16.f32 "
        "{%0,%1,%2,%3}, {%4,%5,%6,%7}, {%8,%9}, {%0,%1,%2,%3};"
        : "+f"(d[0]), "+f"(d[1]), "+f"(d[2]), "+f"(d[3])
        : "r"(a[0]), "r"(a[1]), "r"(a[2]), "r"(a[3]), "r"(b0), "r"(b1));
}

// ---------------------------------------------------------------------------
__global__ void prep_w(const float* __restrict__ w1, const float* __restrict__ w2,
                       const float* __restrict__ w3, const float* __restrict__ w4) {
    const int total = 36 * 256 * 512;
    for (int idx = blockIdx.x * blockDim.x + threadIdx.x; idx < total;
         idx += gridDim.x * blockDim.x) {
        int ci = idx & 511, co = (idx >> 9) & 255;
        int tap = (idx >> 17) % 9, conv = idx / (9 << 17);
        int dy = tap / 3, dx = tap % 3;
        int kh = 3 - (conv & 1), kw = 3 - ((conv >> 1) & 1);
        float v = 0.f;
        if (dy < kh && dx < kw) {
            const float* w = (conv == 0) ? w1 : (conv == 1) ? w2 : (conv == 2) ? w3 : w4;
            v = w[((co * CIN + ci) * kh + dy) * kw + dx];
        }
        g_B[idx] = __float2half(v);
    }
}

// im2col: x -> K-major fp16 [tap][p][ci]; grid (8, 16, 9), 256 thr
__global__ void prep_a(const float* __restrict__ x) {
    __shared__ float S[128][33];
    const int rb = blockIdx.x, n = blockIdx.y, tap = blockIdx.z;
    const int dy = tap / 3, dx = tap % 3;
    const int tid = threadIdx.x;
    const size_t outbase = (size_t)tap * 16384 * 512 + ((size_t)n * 1024 + rb * 128) * 512;
    for (int cic = 0; cic < 16; cic++) {
        const int ci0 = cic * 32;
        __syncthreads();
#pragma unroll
        for (int k = 0; k < 16; k++) {
            int idx = tid + k * 256;
            int ci = idx >> 7, pl = idx & 127;
            int i = rb * 4 + (pl >> 5), j = pl & 31;
            int ii = i - 1 + dy, jj = j - 1 + dx;
            float v = 0.f;
            if (ii >= 0 && ii < HH && (unsigned)jj < (unsigned)WW)
                v = x[(((size_t)n * CIN + ci0 + ci) * HH + ii) * WW + jj];
            S[pl][ci] = v;
        }
        __syncthreads();
#pragma unroll
        for (int k = 0; k < 16; k++) {
            int idx = tid + k * 256;
            int pl = idx >> 5, ci = idx & 31;
            g_A[outbase + (size_t)pl * 512 + ci0 + ci] = __float2half(S[pl][ci]);
        }
    }
}

// ---------------------------------------------------------------------------
// Stage load: burst whole A tile then whole B tile (round-4 proven pattern)
__device__ __forceinline__ void load_stage(uint32_t sb, int conv, int p0, int c0, int s, int tid) {
    const int tap = c_taps[conv][s >> 3];
    const int ci0 = (s & 7) << 6;
    const uint32_t stage = sb + (uint32_t)(s % NSTG) * STAGEB;
#pragma unroll
    for (int k = 0; k < 8; k++) {
        int i = tid + k * 256;
        int tile = i >> 10;  // 0 = A, 1 = B (uniform per k)
        int rem = i & 1023;
        int row = rem >> 3, seg = rem & 7;
        uint32_t dst = stage + tile * TILEB + row * ROWB + seg * 16;
        const __half* src = (tile == 0)
            ? g_A + ((size_t)tap * 16384 + p0 + row) * 512 + ci0 + seg * 8
            : g_B + ((size_t)(conv * 9 + tap) * 256 + c0 + row) * 512 + ci0 + seg * 8;
        cpa(dst, src);
    }
}

__global__ __launch_bounds__(256, 1)
void conv_mma(const float* __restrict__ b1, const float* __restrict__ b2,
              const float* __restrict__ b3, const float* __restrict__ b4) {
    extern __shared__ char smem[];
    const uint32_t sb = smem_u32(smem);
    const int tid = threadIdx.x, wid = tid >> 5, lane = tid & 31;
    const int conv = blockIdx.x >> 8;
    const int c0 = ((blockIdx.x >> 7) & 1) * 128;
    const int p0 = (blockIdx.x & 127) * 128;
    const int S = c_ntaps[conv] * 8;

    const int m0 = (wid & 3) * 32;
    const int n0 = (wid >> 2) * 64;

    float d[2][8][4];
#pragma unroll
    for (int mt = 0; mt < 2; mt++)
#pragma unroll
        for (int nt = 0; nt < 8; nt++)
#pragma unroll
            for (int e = 0; e < 4; e++) d[mt][nt][e] = 0.f;

#pragma unroll
    for (int s = 0; s < NSTG - 1; s++) {
        load_stage(sb, conv, p0, c0, s, tid);  // S >= 32 always, no bound check needed
        asm volatile("cp.async.commit_group;");
    }

    for (int s = 0; s < S; s++) {
        if (s + NSTG - 1 < S) {
            load_stage(sb, conv, p0, c0, s + NSTG - 1, tid);
            asm volatile("cp.async.commit_group;");
            asm volatile("cp.async.wait_group %0;" :: "n"(NSTG - 1));
        } else {
            // remaining in-flight groups: S-1-s target
            switch (S - 1 - s) {
                case 2: asm volatile("cp.async.wait_group 2;"); break;
                case 1: asm volatile("cp.async.wait_group 1;"); break;
                default: asm volatile("cp.async.wait_group 0;"); break;
            }
        }
        __syncthreads();

        const uint32_t stage = sb + (uint32_t)(s % NSTG) * STAGEB;
        uint32_t a[2][4], b[16];
#pragma unroll
        for (int kk = 0; kk < 4; kk++) {
            const uint32_t arow = m0 + (lane & 15);
            const uint32_t akof = kk * 32 + ((lane >> 4) << 4);
            uint32_t aa = stage + arow * ROWB + akof;
            ldsm4(a[0][0], a[0][1], a[0][2], a[0][3], aa);
            ldsm4(a[1][0], a[1][1], a[1][2], a[1][3], aa + 16 * ROWB);
            const uint32_t brow = n0 + ((lane >> 4) << 3) + (lane & 7);
            const uint32_t bkof = kk * 32 + (((lane >> 3) & 1) << 4);
#pragma unroll
            for (int bt = 0; bt < 4; bt++) {
                uint32_t ba = stage + TILEB + (brow + bt * 16) * ROWB + bkof;
                ldsm4(b[bt * 4], b[bt * 4 + 1], b[bt * 4 + 2], b[bt * 4 + 3], ba);
            }
#pragma unroll
            for (int mt = 0; mt < 2; mt++)
#pragma unroll
                for (int nt = 0; nt < 8; nt++)
                    mma_f16(d[mt][nt], a[mt], b[nt * 2], b[nt * 2 + 1]);
        }
        __syncthreads();
    }

    // Epilogue: add bias, store to scratch
    const float* bias = (conv == 0) ? b1 : (conv == 1) ? b2 : (conv == 2) ? b3 : b4;
#pragma unroll
    for (int mt = 0; mt < 2; mt++)
#pragma unroll
        for (int nt = 0; nt < 8; nt++) {
            int prow = p0 + m0 + mt * 16 + (lane >> 2);
            int co = c0 + n0 + nt * 8 + (lane & 3) * 2;
            float bv0 = __ldg(bias + co), bv1 = __ldg(bias + co + 1);
            size_t base = ((size_t)(conv * NB + (prow >> 10)) * COUT + co) * 1024 + (prow & 1023);
            g_scratch[base]            = d[mt][nt][0] + bv0;
            g_scratch[base + 1024]     = d[mt][nt][1] + bv1;
            g_scratch[base + 8]        = d[mt][nt][2] + bv0;
            g_scratch[base + 1024 + 8] = d[mt][nt][3] + bv1;
        }
}

// BN stats: one block per channel, deterministic tree reduction
__global__ void stats_k(const float* __restrict__ gamma, const float* __restrict__ beta) {
    __shared__ float sS[256], sQ[256];
    const int c = blockIdx.x, tid = threadIdx.x;
    float S = 0.f, Q = 0.f;
    for (int idx = tid; idx < 65536; idx += 256) {
        int sp = idx & 1023, cn = idx >> 10;
        float v = g_scratch[((size_t)cn * COUT + c) * 1024 + sp];
        S += v; Q += v * v;
    }
    sS[tid] = S; sQ[tid] = Q;
    __syncthreads();
    for (int off = 128; off > 0; off >>= 1) {
        if (tid < off) { sS[tid] += sS[tid + off]; sQ[tid] += sQ[tid + off]; }
        __syncthreads();
    }
    if (tid == 0) {
        const float inv = 1.f / 65536.f;
        float mean = sS[0] * inv;
        float var = sQ[0] * inv - mean * mean;
        float sc = gamma[c] * rsqrtf(var + EPSV);
        g_scale[c] = sc;
        g_shift[c] = beta[c] - mean * sc;
    }
}

__global__ void apply_k(float* __restrict__ out) {
    int t = blockIdx.x * blockDim.x + threadIdx.x;
    int base = t * 4;
    if (base >= NB * COUT * 64 * 64) return;
    int J0 = base & 63, I = (base >> 6) & 63, c = (base >> 12) & 255, n = base >> 20;
    int i = I >> 1, pr = I & 1;
    float sc = g_scale[c], sh = g_shift[c];
    float v[4];
#pragma unroll
    for (int e = 0; e < 4; e++) {
        int J = J0 + e;
        int conv = pr + ((J & 1) << 1);
        int j = J >> 1;
        float o = g_scratch[((((size_t)conv * NB + n) * COUT + c) * HH + i) * WW + j];
        float y = o * sc + sh;
        v[e] = y > 0.f ? y : 0.f;
    }
    *(float4*)(out + base) = make_float4(v[0], v[1], v[2], v[3]);
}

extern "C" void kernel_launch(void* const* d_in, const int* in_sizes, int n_in,
                              void* d_out, int out_size) {
    const float* x     = (const float*)d_in[0];
    const float* w1    = (const float*)d_in[1];
    const float* b1    = (const float*)d_in[2];
    const float* w2    = (const float*)d_in[3];
    const float* b2    = (const float*)d_in[4];
    const float* w3    = (const float*)d_in[5];
    const float* b3    = (const float*)d_in[6];
    const float* w4    = (const float*)d_in[7];
    const float* b4    = (const float*)d_in[8];
    const float* gamma = (const float*)d_in[9];
    const float* beta  = (const float*)d_in[10];
    float* out = (float*)d_out;

    cudaFuncSetAttribute(conv_mma, cudaFuncAttributeMaxDynamicSharedMemorySize, SMEM_SZ);
    prep_w<<<1024, 256>>>(w1, w2, w3, w4);
    prep_a<<<dim3(8, 16, 9), 256>>>(x);
    conv_mma<<<1024, 256, SMEM_SZ>>>(b1, b2, b3, b4);
    stats_k<<<COUT, 256>>>(gamma, beta);
    apply_k<<<(NB * COUT * 64 * 64 / 4 + 255) / 256, 256>>>(out);
}

// round 7
// speedup vs baseline: 2.7377x; 1.0102x over previous
#include <cuda_runtime.h>
#include <cuda_fp16.h>
#include <cstdint>

#define NB 16
#define CIN 512
#define COUT 256
#define HH 32
#define WW 32
#define EPSV 1e-5f

__device__ __align__(16) __half g_A[9ull * 16384 * 512];   // im2col fp16 [tap][p][ci]
__device__ __align__(16) __half g_B[36ull * 256 * 512];    // fp16 [(conv*9+tap)][co][ci]
__device__ float g_scratch[4ull * NB * COUT * HH * WW];    // [conv][n][c][1024]
__device__ float g_scale[COUT];
__device__ float g_shift[COUT];

__constant__ int c_taps[4][9] = {
    {0,1,2,3,4,5,6,7,8}, {0,1,2,3,4,5,0,0,0}, {0,1,3,4,6,7,0,0,0}, {0,1,3,4,0,0,0,0,0}};
__constant__ int c_ntaps[4] = {9, 6, 6, 4};

__device__ __forceinline__ uint32_t smem_u32(const void* p) {
    uint32_t a;
    asm("{ .reg .u64 t; cvta.to.shared.u64 t, %1; cvt.u32.u64 %0, t; }" : "=r"(a) : "l"(p));
    return a;
}

#define ROWB   144u     // 128B data + 16B pad
#define ATILEB 18432u   // 128 * 144
#define BTILEB 36864u   // 256 * 144
#define STAGEB 55296u   // A tile + B tile
#define NSTG 4
#define SMEM_SZ (NSTG * STAGEB)   // 216 KB

__device__ __forceinline__ void cpa(uint32_t dst, const void* src) {
    asm volatile("cp.async.cg.shared.global [%0], [%1], 16;" :: "r"(dst), "l"(src));
}
__device__ __forceinline__ void ldsm4(uint32_t& r0, uint32_t& r1, uint32_t& r2, uint32_t& r3,
                                      uint32_t a) {
    asm volatile("ldmatrix.sync.aligned.m8n8.x4.shared.b16 {%0,%1,%2,%3}, [%4];"
                 : "=r"(r0), "=r"(r1), "=r"(r2), "=r"(r3) : "r"(a));
}
__device__ __forceinline__ void mma_f16(float* d, const uint32_t* a, uint32_t b0, uint32_t b1) {
    asm volatile(
        "mma.sync.aligned.m16n8k16.row.col.f32.f16.f16.f32 "
        "{%0,%1,%2,%3}, {%4,%5,%6,%7}, {%8,%9}, {%0,%1,%2,%3};"
        : "+f"(d[0]), "+f"(d[1]), "+f"(d[2]), "+f"(d[3])
        : "r"(a[0]), "r"(a[1]), "r"(a[2]), "r"(a[3]), "r"(b0), "r"(b1));
}

// ---------------------------------------------------------------------------
__global__ void prep_w(const float* __restrict__ w1, const float* __restrict__ w2,
                       const float* __restrict__ w3, const float* __restrict__ w4) {
    const int total = 36 * 256 * 512;
    for (int idx = blockIdx.x * blockDim.x + threadIdx.x; idx < total;
         idx += gridDim.x * blockDim.x) {
        int ci = idx & 511, co = (idx >> 9) & 255;
        int tap = (idx >> 17) % 9, conv = idx / (9 << 17);
        int dy = tap / 3, dx = tap % 3;
        int kh = 3 - (conv & 1), kw = 3 - ((conv >> 1) & 1);
        float v = 0.f;
        if (dy < kh && dx < kw) {
            const float* w = (conv == 0) ? w1 : (conv == 1) ? w2 : (conv == 2) ? w3 : w4;
            v = w[((co * CIN + ci) * kh + dy) * kw + dx];
        }
        g_B[idx] = __float2half(v);
    }
}

// im2col: x -> K-major fp16 [tap][p][ci]; grid (8, 16, 9)
__global__ void prep_a(const float* __restrict__ x) {
    __shared__ float S[128][33];
    const int rb = blockIdx.x, n = blockIdx.y, tap = blockIdx.z;
    const int dy = tap / 3, dx = tap % 3;
    const int tid = threadIdx.x;
    const size_t outbase = (size_t)tap * 16384 * 512 + ((size_t)n * 1024 + rb * 128) * 512;
    for (int cic = 0; cic < 16; cic++) {
        const int ci0 = cic * 32;
        __syncthreads();
#pragma unroll
        for (int k = 0; k < 16; k++) {
            int idx = tid + k * 256;
            int ci = idx >> 7, pl = idx & 127;
            int i = rb * 4 + (pl >> 5), j = pl & 31;
            int ii = i - 1 + dy, jj = j - 1 + dx;
            float v = 0.f;
            if (ii >= 0 && ii < HH && (unsigned)jj < (unsigned)WW)
                v = x[(((size_t)n * CIN + ci0 + ci) * HH + ii) * WW + jj];
            S[pl][ci] = v;
        }
        __syncthreads();
#pragma unroll
        for (int k = 0; k < 16; k++) {
            int idx = tid + k * 256;
            int pl = idx >> 5, ci = idx & 31;
            g_A[outbase + (size_t)pl * 512 + ci0 + ci] = __float2half(S[pl][ci]);
        }
    }
}

// ---------------------------------------------------------------------------
// Stage: A 128x64 (1024 cp.async) then B 256x64 (2048 cp.async)
__device__ __forceinline__ void load_stage(uint32_t sb, int conv, int p0, int s, int tid) {
    const int tap = c_taps[conv][s >> 3];
    const int ci0 = (s & 7) << 6;
    const uint32_t stage = sb + (uint32_t)(s % NSTG) * STAGEB;
    const size_t abase = ((size_t)tap * 16384 + p0) * 512 + ci0;
    const size_t bbase = ((size_t)(conv * 9 + tap) * 256) * 512 + ci0;
#pragma unroll
    for (int k = 0; k < 12; k++) {
        int i = tid + k * 256;
        int row, seg;
        uint32_t dst;
        const __half* src;
        if (i < 1024) {               // uniform per k (k<4)
            row = i >> 3; seg = i & 7;
            dst = stage + row * ROWB + seg * 16;
            src = g_A + abase + (size_t)row * 512 + seg * 8;
        } else {
            int j = i - 1024;
            row = j >> 3; seg = j & 7;
            dst = stage + ATILEB + row * ROWB + seg * 16;
            src = g_B + bbase + (size_t)row * 512 + seg * 8;
        }
        cpa(dst, src);
    }
}

__global__ __launch_bounds__(256, 1)
void conv_mma(const float* __restrict__ b1, const float* __restrict__ b2,
              const float* __restrict__ b3, const float* __restrict__ b4) {
    extern __shared__ char smem[];
    const uint32_t sb = smem_u32(smem);
    const int tid = threadIdx.x, wid = tid >> 5, lane = tid & 31;
    const int conv = blockIdx.x & 3;          // interleave heavy/light CTAs
    const int p0 = (blockIdx.x >> 2) * 128;
    const int S = c_ntaps[conv] * 8;

    const int m0 = (wid & 1) * 64;
    const int n0 = (wid >> 1) * 64;

    float d[4][8][4];
#pragma unroll
    for (int mt = 0; mt < 4; mt++)
#pragma unroll
        for (int nt = 0; nt < 8; nt++)
#pragma unroll
            for (int e = 0; e < 4; e++) d[mt][nt][e] = 0.f;

#pragma unroll
    for (int s = 0; s < NSTG - 1; s++) {
        load_stage(sb, conv, p0, s, tid);   // S >= 32 always
        asm volatile("cp.async.commit_group;");
    }

    for (int s = 0; s < S; s++) {
        if (s + NSTG - 1 < S) {
            load_stage(sb, conv, p0, s + NSTG - 1, tid);
            asm volatile("cp.async.commit_group;");
            asm volatile("cp.async.wait_group %0;" :: "n"(NSTG - 1));
        } else {
            switch (S - 1 - s) {
                case 2: asm volatile("cp.async.wait_group 2;"); break;
                case 1: asm volatile("cp.async.wait_group 1;"); break;
                default: asm volatile("cp.async.wait_group 0;"); break;
            }
        }
        __syncthreads();

        const uint32_t stage = sb + (uint32_t)(s % NSTG) * STAGEB;
        uint32_t a[4][4], b[16];
#pragma unroll
        for (int kk = 0; kk < 4; kk++) {
            const uint32_t arow = m0 + (lane & 15);
            const uint32_t akof = kk * 32 + ((lane >> 4) << 4);
            uint32_t aa = stage + arow * ROWB + akof;
#pragma unroll
            for (int mt = 0; mt < 4; mt++)
                ldsm4(a[mt][0], a[mt][1], a[mt][2], a[mt][3], aa + mt * 16 * ROWB);
            const uint32_t brow = n0 + ((lane >> 4) << 3) + (lane & 7);
            const uint32_t bkof = kk * 32 + (((lane >> 3) & 1) << 4);
#pragma unroll
            for (int bt = 0; bt < 4; bt++) {
                uint32_t ba = stage + ATILEB + (brow + bt * 16) * ROWB + bkof;
                ldsm4(b[bt * 4], b[bt * 4 + 1], b[bt * 4 + 2], b[bt * 4 + 3], ba);
            }
#pragma unroll
            for (int mt = 0; mt < 4; mt++)
#pragma unroll
                for (int nt = 0; nt < 8; nt++)
                    mma_f16(d[mt][nt], a[mt], b[nt * 2], b[nt * 2 + 1]);
        }
        __syncthreads();
    }

    // Epilogue: add bias, store to scratch
    const float* bias = (conv == 0) ? b1 : (conv == 1) ? b2 : (conv == 2) ? b3 : b4;
#pragma unroll
    for (int mt = 0; mt < 4; mt++)
#pragma unroll
        for (int nt = 0; nt < 8; nt++) {
            int prow = p0 + m0 + mt * 16 + (lane >> 2);
            int co = n0 + nt * 8 + (lane & 3) * 2;
            float bv0 = __ldg(bias + co), bv1 = __ldg(bias + co + 1);
            size_t base = ((size_t)(conv * NB + (prow >> 10)) * COUT + co) * 1024 + (prow & 1023);
            g_scratch[base]            = d[mt][nt][0] + bv0;
            g_scratch[base + 1024]     = d[mt][nt][1] + bv1;
            g_scratch[base + 8]        = d[mt][nt][2] + bv0;
            g_scratch[base + 1024 + 8] = d[mt][nt][3] + bv1;
        }
}

// BN stats: one block per channel, deterministic tree reduction
__global__ void stats_k(const float* __restrict__ gamma, const float* __restrict__ beta) {
    __shared__ float sS[256], sQ[256];
    const int c = blockIdx.x, tid = threadIdx.x;
    float S = 0.f, Q = 0.f;
    for (int idx = tid; idx < 65536; idx += 256) {
        int sp = idx & 1023, cn = idx >> 10;
        float v = g_scratch[((size_t)cn * COUT + c) * 1024 + sp];
        S += v; Q += v * v;
    }
    sS[tid] = S; sQ[tid] = Q;
    __syncthreads();
    for (int off = 128; off > 0; off >>= 1) {
        if (tid < off) { sS[tid] += sS[tid + off]; sQ[tid] += sQ[tid + off]; }
        __syncthreads();
    }
    if (tid == 0) {
        const float inv = 1.f / 65536.f;
        float mean = sS[0] * inv;
        float var = sQ[0] * inv - mean * mean;
        float sc = gamma[c] * rsqrtf(var + EPSV);
        g_scale[c] = sc;
        g_shift[c] = beta[c] - mean * sc;
    }
}

__global__ void apply_k(float* __restrict__ out) {
    int t = blockIdx.x * blockDim.x + threadIdx.x;
    int base = t * 4;
    if (base >= NB * COUT * 64 * 64) return;
    int J0 = base & 63, I = (base >> 6) & 63, c = (base >> 12) & 255, n = base >> 20;
    int i = I >> 1, pr = I & 1;
    float sc = g_scale[c], sh = g_shift[c];
    float v[4];
#pragma unroll
    for (int e = 0; e < 4; e++) {
        int J = J0 + e;
        int conv = pr + ((J & 1) << 1);
        int j = J >> 1;
        float o = g_scratch[((((size_t)conv * NB + n) * COUT + c) * HH + i) * WW + j];
        float y = o * sc + sh;
        v[e] = y > 0.f ? y : 0.f;
    }
    *(float4*)(out + base) = make_float4(v[0], v[1], v[2], v[3]);
}

extern "C" void kernel_launch(void* const* d_in, const int* in_sizes, int n_in,
                              void* d_out, int out_size) {
    const float* x     = (const float*)d_in[0];
    const float* w1    = (const float*)d_in[1];
    const float* b1    = (const float*)d_in[2];
    const float* w2    = (const float*)d_in[3];
    const float* b2    = (const float*)d_in[4];
    const float* w3    = (const float*)d_in[5];
    const float* b3    = (const float*)d_in[6];
    const float* w4    = (const float*)d_in[7];
    const float* b4    = (const float*)d_in[8];
    const float* gamma = (const float*)d_in[9];
    const float* beta  = (const float*)d_in[10];
    float* out = (float*)d_out;

    cudaFuncSetAttribute(conv_mma, cudaFuncAttributeMaxDynamicSharedMemorySize, SMEM_SZ);
    prep_w<<<1024, 256>>>(w1, w2, w3, w4);
    prep_a<<<dim3(8, 16, 9), 256>>>(x);
    conv_mma<<<512, 256, SMEM_SZ>>>(b1, b2, b3, b4);
    stats_k<<<COUT, 256>>>(gamma, beta);
    apply_k<<<(NB * COUT * 64 * 64 / 4 + 255) / 256, 256>>>(out);
}